// round 14
// baseline (speedup 1.0000x reference)
#include <cuda_runtime.h>
#include <cuda_bf16.h>
#include <cstdint>

#define BATCH 4
#define CH    128
#define HH    128
#define WW    128
#define COUT  128
#define HWSZ  (HH*WW)

// Scratch (static __device__ arrays: allocation-free per harness rules)
__device__ float g_xT[BATCH*HWSZ*CH];          // x channels-last [b][h][w][c]
__device__ float g_off[BATCH*HWSZ*18];         // offsets [b][h][w][18]
__device__ float g_wo[9*CH*18];                // w_off reordered [k][c][co]
__device__ __nv_bfloat16 g_wtb_hi[9*COUT*CH];  // w_def bf16 hi, [k][co][c]
__device__ __nv_bfloat16 g_wtb_lo[9*COUT*CH];  // w_def bf16 lo, [k][co][c]

// ---------- f32x2 helpers (k_offconv only) ----------
__device__ __forceinline__ unsigned long long pack2(float x, float y) {
    unsigned long long r;
    asm("mov.b64 %0, {%1, %2};" : "=l"(r) : "f"(x), "f"(y));
    return r;
}
__device__ __forceinline__ void fma2(unsigned long long& d, unsigned long long a, unsigned long long b) {
    asm("fma.rn.f32x2 %0, %1, %2, %0;" : "+l"(d) : "l"(a), "l"(b));
}
__device__ __forceinline__ float2 unpack2(unsigned long long v) {
    float2 f;
    asm("mov.b64 {%0, %1}, %2;" : "=f"(f.x), "=f"(f.y) : "l"(v));
    return f;
}

// ---------- mma.sync helpers (sm_80+ PTX; works at compute_103 target) ----------
__device__ __forceinline__ uint32_t smem_u32(const void* p) {
    uint32_t a;
    asm("{ .reg .u64 t; cvta.to.shared.u64 t, %1; cvt.u32.u64 %0, t; }" : "=r"(a) : "l"(p));
    return a;
}
__device__ __forceinline__ void ldsm4(unsigned* r, uint32_t addr) {
    asm volatile("ldmatrix.sync.aligned.m8n8.x4.shared.b16 {%0,%1,%2,%3}, [%4];"
        : "=r"(r[0]), "=r"(r[1]), "=r"(r[2]), "=r"(r[3]) : "r"(addr));
}
__device__ __forceinline__ void mma16816(float* d, const unsigned* a, const unsigned* b) {
    asm volatile(
        "mma.sync.aligned.m16n8k16.row.col.f32.bf16.bf16.f32 "
        "{%0,%1,%2,%3}, {%4,%5,%6,%7}, {%8,%9}, {%0,%1,%2,%3};"
        : "+f"(d[0]), "+f"(d[1]), "+f"(d[2]), "+f"(d[3])
        : "r"(a[0]), "r"(a[1]), "r"(a[2]), "r"(a[3]), "r"(b[0]), "r"(b[1]));
}

// ---------- kernel 1: transpose x -> channels-last ----------
__global__ void k_transpose(const float* __restrict__ x) {
    __shared__ float tile[32][33];
    int b  = blockIdx.z;
    int c0 = blockIdx.y * 32;
    int p0 = blockIdx.x * 32;
    int tx = threadIdx.x, ty = threadIdx.y;
    const float* xb = x + (size_t)b * CH * HWSZ;
    #pragma unroll
    for (int j = 0; j < 32; j += 8)
        tile[ty + j][tx] = xb[(c0 + ty + j) * HWSZ + p0 + tx];
    __syncthreads();
    float* ob = g_xT + (size_t)b * HWSZ * CH;
    #pragma unroll
    for (int j = 0; j < 32; j += 8)
        ob[(p0 + ty + j) * CH + c0 + tx] = tile[tx][ty + j];
}

// ---------- kernel 2a: w_def -> bf16 hi/lo [k][co][c] ----------
__global__ void k_reorder_wdefb(const float* __restrict__ wdef) {
    int i = blockIdx.x * 256 + threadIdx.x;
    if (i >= 9 * COUT * CH) return;
    int k  = i / (COUT * CH);
    int r  = i % (COUT * CH);
    int co = r / CH, c = r % CH;
    float v = wdef[(co * CH + c) * 9 + k];
    __nv_bfloat16 hi = __float2bfloat16(v);
    __nv_bfloat16 lo = __float2bfloat16(v - __bfloat162float(hi));
    g_wtb_hi[i] = hi;
    g_wtb_lo[i] = lo;
}
// ---------- kernel 2b: w_off reorder ----------
__global__ void k_reorder_woff(const float* __restrict__ woff) {
    int i = blockIdx.x * 256 + threadIdx.x;
    if (i >= 9 * CH * 18) return;
    int k = i / (CH * 18);
    int r = i % (CH * 18);
    int c = r / 18, co = r % 18;
    g_wo[i] = woff[(co * CH + c) * 9 + k];
}

// ---------- kernel 3: offset conv — vectorized weight LDS (5 loads vs 9 per c) ----------
// rowbuf padded to 16772 floats so wsk is 16B-aligned; wsk rows padded to 20 floats.
#define RBUF_FLOATS 16772
#define SMEM_B_FLOATS (RBUF_FLOATS + 3*CH*20)
__global__ void __launch_bounds__(256, 2) k_offconv(const float* __restrict__ b_off) {
    extern __shared__ float sm[];
    float* rowbuf  = sm;                    // [pos 0..129][129]
    float* wsk     = sm + RBUF_FLOATS;      // [kx][c][20] (18 used, 16B-aligned rows)
    float* partial = wsk;                   // aliased after compute
    int h = blockIdx.x, b = blockIdx.y;
    int tid  = threadIdx.x;
    int lane = tid & 31, wrp = tid >> 5;
    int px    = tid & 127;
    int chalf = tid >> 7;
    int c0    = chalf * 64;

    unsigned long long acc[9];
    #pragma unroll
    for (int j = 0; j < 9; j++) acc[j] = 0ULL;

    for (int ky = 0; ky < 3; ky++) {
        int y = h + ky - 1;
        if ((unsigned)y >= HH) continue;
        __syncthreads();
        const float* src = g_xT + ((size_t)(b * HH + y) * WW) * CH;
        for (int pos = wrp; pos < 130; pos += 8) {
            int x = pos - 1;
            float4 v = make_float4(0.f, 0.f, 0.f, 0.f);
            if ((unsigned)x < WW) v = *(const float4*)(src + x * CH + 4 * lane);
            float* dst = rowbuf + pos * 129 + 4 * lane;
            dst[0] = v.x; dst[1] = v.y; dst[2] = v.z; dst[3] = v.w;
        }
        for (int i = tid; i < 3 * CH * 18; i += 256)
            wsk[(i / 18) * 20 + (i % 18)] = g_wo[ky * 3 * CH * 18 + i];
        __syncthreads();
        #pragma unroll
        for (int kx = 0; kx < 3; kx++) {
            const float* wk = wsk + kx * CH * 20;
            const float* rb = rowbuf + (px + kx) * 129;
            #pragma unroll 2
            for (int cc = 0; cc < 64; cc++) {
                int c = c0 + cc;
                float xv = rb[c];
                unsigned long long xv2 = pack2(xv, xv);
                const ulonglong2* w2 = (const ulonglong2*)(wk + c * 20);
                ulonglong2 wa = w2[0], wb = w2[1], wc = w2[2], wd = w2[3];
                unsigned long long we = *(const unsigned long long*)(wk + c * 20 + 16);
                fma2(acc[0], xv2, wa.x); fma2(acc[1], xv2, wa.y);
                fma2(acc[2], xv2, wb.x); fma2(acc[3], xv2, wb.y);
                fma2(acc[4], xv2, wc.x); fma2(acc[5], xv2, wc.y);
                fma2(acc[6], xv2, wd.x); fma2(acc[7], xv2, wd.y);
                fma2(acc[8], xv2, we);
            }
        }
    }
    __syncthreads();
    if (chalf == 1) {
        float* p = partial + px * 19;
        #pragma unroll
        for (int j = 0; j < 9; j++) {
            float2 v = unpack2(acc[j]);
            p[2 * j] = v.x; p[2 * j + 1] = v.y;
        }
    }
    __syncthreads();
    if (chalf == 0) {
        const float* p = partial + px * 19;
        int base = ((b * HH + h) * WW + px) * 18;
        #pragma unroll
        for (int j = 0; j < 9; j++) {
            float2 v = unpack2(acc[j]);
            g_off[base + 2 * j]     = v.x + p[2 * j]     + b_off[2 * j];
            g_off[base + 2 * j + 1] = v.y + p[2 * j + 1] + b_off[2 * j + 1];
        }
    }
}

// ---------- kernel 4: mma.sync bf16-split deformable conv + gate ----------
// 64-px blocks: 128 threads (4 warps, m16n128 each), 110KB smem -> 2 CTAs/SM.
// Cross-CTA overlap hides sampling LDG latency under the other CTA's GEMM issue.
#define MTILE    64
#define LDA      136
#define LDAB     (LDA*2)          // 272 bytes per row
#define A_BYTES  (MTILE*LDAB)     // 17408
#define B_BYTES  (128*LDAB)       // 34816
#define OFF_OFFS  0               // 64*18*4 = 4608
#define OFF_BDEF  4608
#define OFF_WATTN 5120
#define OFF_A_HI  5632
#define OFF_A_LO  (OFF_A_HI + A_BYTES)
#define OFF_B_HI  (OFF_A_LO + A_BYTES)
#define OFF_B_LO  (OFF_B_HI + B_BYTES)
#define SMEM_MAIN_BYTES (OFF_B_LO + B_BYTES)   // 110080

__global__ void __launch_bounds__(128, 2) k_main(const float* __restrict__ bdef,
                                                 const float* __restrict__ wattn,
                                                 const float* __restrict__ battn,
                                                 float* __restrict__ out) {
    extern __shared__ char smc[];
    uint32_t sb = smem_u32(smc);
    int h   = blockIdx.x >> 1;
    int px0 = (blockIdx.x & 1) << 6;
    int b   = blockIdx.y;
    int tid = threadIdx.x, lane = tid & 31, wid = tid >> 5;

    float* offs   = (float*)(smc + OFF_OFFS);
    float* sbdef  = (float*)(smc + OFF_BDEF);
    float* swattn = (float*)(smc + OFF_WATTN);

    for (int i = tid; i < 128; i += 128) { sbdef[i] = bdef[i]; swattn[i] = wattn[i]; }
    {
        const float* src = g_off + ((size_t)((b * HH + h) * WW) + px0) * 18;
        for (int i = tid; i < MTILE * 18; i += 128) offs[i] = src[i];
    }

    float acc[16][4];
    #pragma unroll
    for (int i = 0; i < 16; i++)
        #pragma unroll
        for (int j = 0; j < 4; j++) acc[i][j] = 0.f;

    const float* xb = g_xT + (size_t)b * HWSZ * CH + 4 * lane;

    // ldmatrix base addresses (rows local to this 64-px tile)
    int m0 = wid * 16;
    uint32_t aHi = sb + OFF_A_HI + (uint32_t)((m0 + (lane & 15)) * LDAB + (lane >> 4) * 16);
    uint32_t aLo = aHi + A_BYTES;
    // B (non-trans): matrices = [n0-7,k0] [n0-7,k8] [n8-15,k0] [n8-15,k8]
    uint32_t bRow = (uint32_t)((lane & 7) + ((lane >> 4) << 3));
    uint32_t bHi = sb + OFF_B_HI + bRow * LDAB + (((lane >> 3) & 1) << 4);
    uint32_t bLo = bHi + B_BYTES;

    for (int k = 0; k < 9; k++) {
        __syncthreads();   // previous-tap GEMM reads done; covers offs/bdef loads on k=0
        {   // stage B hi/lo: [co][c] -> padded rows
            const uint4* sh = (const uint4*)(g_wtb_hi + (size_t)k * COUT * CH);
            const uint4* sl = (const uint4*)(g_wtb_lo + (size_t)k * COUT * CH);
            for (int i = tid; i < 2048; i += 128) {
                int row = i >> 4, c8 = i & 15;
                *(uint4*)(smc + OFF_B_HI + row * LDAB + c8 * 16) = sh[i];
                *(uint4*)(smc + OFF_B_LO + row * LDAB + c8 * 16) = sl[i];
            }
        }
        // sample A (warp: 16 px, lane: channel quad), split fp32 -> bf16 hi+lo
        int ky = k / 3, kx = k % 3;
        #pragma unroll 2
        for (int it = 0; it < 16; it++) {
            int pl = wid * 16 + it;          // local row in A tile
            int px = px0 + pl;               // global pixel x
            float dy = offs[pl * 18 + 2 * k];
            float dx = offs[pl * 18 + 2 * k + 1];
            float ysf = (float)(h - 1 + ky) + dy;
            float xsf = (float)(px - 1 + kx) + dx;
            float y0f = floorf(ysf), x0f = floorf(xsf);
            float wy = ysf - y0f, wx = xsf - x0f;
            int y0 = (int)y0f, x0 = (int)x0f;
            float w00 = (1.f - wy) * (1.f - wx);
            float w01 = (1.f - wy) * wx;
            float w10 = wy * (1.f - wx);
            float w11 = wy * wx;
            float4 v = make_float4(0.f, 0.f, 0.f, 0.f);
            #define TAPG(Y, X, WGT) \
                if ((unsigned)(Y) < HH && (unsigned)(X) < WW) { \
                    float4 t = *(const float4*)(xb + ((Y) * WW + (X)) * CH); \
                    v.x = fmaf(WGT, t.x, v.x); v.y = fmaf(WGT, t.y, v.y); \
                    v.z = fmaf(WGT, t.z, v.z); v.w = fmaf(WGT, t.w, v.w); }
            TAPG(y0,     x0,     w00)
            TAPG(y0,     x0 + 1, w01)
            TAPG(y0 + 1, x0,     w10)
            TAPG(y0 + 1, x0 + 1, w11)
            #undef TAPG
            __nv_bfloat16 h0 = __float2bfloat16(v.x);
            __nv_bfloat16 h1 = __float2bfloat16(v.y);
            __nv_bfloat16 h2 = __float2bfloat16(v.z);
            __nv_bfloat16 h3 = __float2bfloat16(v.w);
            __nv_bfloat16 l0 = __float2bfloat16(v.x - __bfloat162float(h0));
            __nv_bfloat16 l1 = __float2bfloat16(v.y - __bfloat162float(h1));
            __nv_bfloat16 l2 = __float2bfloat16(v.z - __bfloat162float(h2));
            __nv_bfloat16 l3 = __float2bfloat16(v.w - __bfloat162float(h3));
            unsigned hu0 = ((unsigned)__bfloat16_as_ushort(h1) << 16) | __bfloat16_as_ushort(h0);
            unsigned hu1 = ((unsigned)__bfloat16_as_ushort(h3) << 16) | __bfloat16_as_ushort(h2);
            unsigned lu0 = ((unsigned)__bfloat16_as_ushort(l1) << 16) | __bfloat16_as_ushort(l0);
            unsigned lu1 = ((unsigned)__bfloat16_as_ushort(l3) << 16) | __bfloat16_as_ushort(l2);
            *(unsigned long long*)(smc + OFF_A_HI + pl * LDAB + 8 * lane) =
                ((unsigned long long)hu1 << 32) | hu0;
            *(unsigned long long*)(smc + OFF_A_LO + pl * LDAB + 8 * lane) =
                ((unsigned long long)lu1 << 32) | lu0;
        }
        __syncthreads();
        // GEMM: 8 K-chunks x 8 n-tile-pairs x 6 mma (AhBh, AhBl, AlBh)
        #pragma unroll
        for (int kc = 0; kc < 8; kc++) {
            unsigned ah[4], al[4];
            ldsm4(ah, aHi + kc * 32);
            ldsm4(al, aLo + kc * 32);
            #pragma unroll
            for (int nt2 = 0; nt2 < 8; nt2++) {
                unsigned bh[4], bl[4];
                ldsm4(bh, bHi + nt2 * (16 * LDAB) + kc * 32);
                ldsm4(bl, bLo + nt2 * (16 * LDAB) + kc * 32);
                float* A0 = acc[nt2 * 2];
                float* A1 = acc[nt2 * 2 + 1];
                mma16816(A0, ah, bh);
                mma16816(A1, ah, bh + 2);
                mma16816(A0, ah, bl);
                mma16816(A1, ah, bl + 2);
                mma16816(A0, al, bh);
                mma16816(A1, al, bh + 2);
            }
        }
    }

    // epilogue (register-only): bias, attention dot + quad shfl reduce, sigmoid, gate, store
    float battn0 = battn[0];
    float p0 = 0.f, p1 = 0.f;
    #pragma unroll
    for (int nt = 0; nt < 16; nt++) {
        int c0 = nt * 8 + (lane & 3) * 2;
        float bb0 = sbdef[c0], bb1 = sbdef[c0 + 1];
        float w0 = swattn[c0], w1 = swattn[c0 + 1];
        acc[nt][0] += bb0; acc[nt][1] += bb1;
        acc[nt][2] += bb0; acc[nt][3] += bb1;
        p0 = fmaf(acc[nt][0], w0, fmaf(acc[nt][1], w1, p0));
        p1 = fmaf(acc[nt][2], w0, fmaf(acc[nt][3], w1, p1));
    }
    p0 += __shfl_xor_sync(0xFFFFFFFFu, p0, 1);
    p0 += __shfl_xor_sync(0xFFFFFFFFu, p0, 2);
    p1 += __shfl_xor_sync(0xFFFFFFFFu, p1, 1);
    p1 += __shfl_xor_sync(0xFFFFFFFFu, p1, 2);
    float sig0 = 1.f / (1.f + expf(-(p0 + battn0)));
    float sig1 = 1.f / (1.f + expf(-(p1 + battn0)));

    int r0 = px0 + m0 + (lane >> 2);
    size_t obase = (size_t)b * COUT * HWSZ + (size_t)h * WW;
    #pragma unroll
    for (int nt = 0; nt < 16; nt++) {
        int c0 = nt * 8 + (lane & 3) * 2;
        out[obase + (size_t)c0       * HWSZ + r0]     = fmaxf(acc[nt][0] * sig0, 0.f);
        out[obase + (size_t)(c0 + 1) * HWSZ + r0]     = fmaxf(acc[nt][1] * sig0, 0.f);
        out[obase + (size_t)c0       * HWSZ + r0 + 8] = fmaxf(acc[nt][2] * sig1, 0.f);
        out[obase + (size_t)(c0 + 1) * HWSZ + r0 + 8] = fmaxf(acc[nt][3] * sig1, 0.f);
    }
}

// ---------- launch ----------
extern "C" void kernel_launch(void* const* d_in, const int* in_sizes, int n_in,
                              void* d_out, int out_size) {
    const float* x      = (const float*)d_in[0];
    const float* w_off  = (const float*)d_in[1];
    const float* b_off  = (const float*)d_in[2];
    const float* w_def  = (const float*)d_in[3];
    const float* b_def  = (const float*)d_in[4];
    const float* w_attn = (const float*)d_in[5];
    const float* b_attn = (const float*)d_in[6];
    float* out = (float*)d_out;

    static bool attrs_set = false;
    if (!attrs_set) {
        cudaFuncSetAttribute(k_offconv, cudaFuncAttributeMaxDynamicSharedMemorySize,
                             SMEM_B_FLOATS * sizeof(float));
        cudaFuncSetAttribute(k_main, cudaFuncAttributeMaxDynamicSharedMemorySize,
                             SMEM_MAIN_BYTES);
        attrs_set = true;
    }

    k_transpose<<<dim3(HWSZ / 32, CH / 32, BATCH), dim3(32, 8)>>>(x);
    k_reorder_wdefb<<<(9 * COUT * CH + 255) / 256, 256>>>(w_def);
    k_reorder_woff<<<(9 * CH * 18 + 255) / 256, 256>>>(w_off);
    k_offconv<<<dim3(HH, BATCH), 256, SMEM_B_FLOATS * sizeof(float)>>>(b_off);
    k_main<<<dim3(HH * 2, BATCH), 128, SMEM_MAIN_BYTES>>>(b_def, w_attn, b_attn, out);
}

// round 17
// speedup vs baseline: 1.3589x; 1.3589x over previous
#include <cuda_runtime.h>
#include <cuda_fp16.h>
#include <cstdint>

#define BATCH 4
#define CH    128
#define HH    128
#define WW    128
#define COUT  128
#define HWSZ  (HH*WW)

// Scratch (static __device__ arrays: allocation-free per harness rules)
__device__ float g_xT[BATCH*HWSZ*CH];     // x channels-last [b][h][w][c]
__device__ float g_off[BATCH*HWSZ*18];    // offsets [b][h][w][18]
__device__ float g_wo[9*CH*18];           // w_off reordered [k][c][co]
__device__ __half g_wtb[9*COUT*CH];       // w_def fp16, [k][co][c]

// ---------- f32x2 helpers (k_offconv only) ----------
__device__ __forceinline__ unsigned long long pack2(float x, float y) {
    unsigned long long r;
    asm("mov.b64 %0, {%1, %2};" : "=l"(r) : "f"(x), "f"(y));
    return r;
}
__device__ __forceinline__ void fma2(unsigned long long& d, unsigned long long a, unsigned long long b) {
    asm("fma.rn.f32x2 %0, %1, %2, %0;" : "+l"(d) : "l"(a), "l"(b));
}
__device__ __forceinline__ float2 unpack2(unsigned long long v) {
    float2 f;
    asm("mov.b64 {%0, %1}, %2;" : "=f"(f.x), "=f"(f.y) : "l"(v));
    return f;
}

// ---------- mma.sync helpers (sm_80+ PTX; works at compute_103 target) ----------
__device__ __forceinline__ uint32_t smem_u32(const void* p) {
    uint32_t a;
    asm("{ .reg .u64 t; cvta.to.shared.u64 t, %1; cvt.u32.u64 %0, t; }" : "=r"(a) : "l"(p));
    return a;
}
__device__ __forceinline__ void ldsm4(unsigned* r, uint32_t addr) {
    asm volatile("ldmatrix.sync.aligned.m8n8.x4.shared.b16 {%0,%1,%2,%3}, [%4];"
        : "=r"(r[0]), "=r"(r[1]), "=r"(r[2]), "=r"(r[3]) : "r"(addr));
}
__device__ __forceinline__ void mma16816h(float* d, const unsigned* a, const unsigned* b) {
    asm volatile(
        "mma.sync.aligned.m16n8k16.row.col.f32.f16.f16.f32 "
        "{%0,%1,%2,%3}, {%4,%5,%6,%7}, {%8,%9}, {%0,%1,%2,%3};"
        : "+f"(d[0]), "+f"(d[1]), "+f"(d[2]), "+f"(d[3])
        : "r"(a[0]), "r"(a[1]), "r"(a[2]), "r"(a[3]), "r"(b[0]), "r"(b[1]));
}
// pack two f32 into f16x2: d.hi = vhi, d.lo = vlo
__device__ __forceinline__ unsigned packh2(float vhi, float vlo) {
    unsigned d;
    asm("cvt.rn.f16x2.f32 %0, %1, %2;" : "=r"(d) : "f"(vhi), "f"(vlo));
    return d;
}

// ---------- kernel 1: transpose x -> channels-last ----------
__global__ void k_transpose(const float* __restrict__ x) {
    __shared__ float tile[32][33];
    int b  = blockIdx.z;
    int c0 = blockIdx.y * 32;
    int p0 = blockIdx.x * 32;
    int tx = threadIdx.x, ty = threadIdx.y;
    const float* xb = x + (size_t)b * CH * HWSZ;
    #pragma unroll
    for (int j = 0; j < 32; j += 8)
        tile[ty + j][tx] = xb[(c0 + ty + j) * HWSZ + p0 + tx];
    __syncthreads();
    float* ob = g_xT + (size_t)b * HWSZ * CH;
    #pragma unroll
    for (int j = 0; j < 32; j += 8)
        ob[(p0 + ty + j) * CH + c0 + tx] = tile[tx][ty + j];
}

// ---------- kernel 2a: w_def -> fp16 [k][co][c] ----------
__global__ void k_reorder_wdefh(const float* __restrict__ wdef) {
    int i = blockIdx.x * 256 + threadIdx.x;
    if (i >= 9 * COUT * CH) return;
    int k  = i / (COUT * CH);
    int r  = i % (COUT * CH);
    int co = r / CH, c = r % CH;
    g_wtb[i] = __float2half_rn(wdef[(co * CH + c) * 9 + k]);
}
// ---------- kernel 2b: w_off reorder ----------
__global__ void k_reorder_woff(const float* __restrict__ woff) {
    int i = blockIdx.x * 256 + threadIdx.x;
    if (i >= 9 * CH * 18) return;
    int k = i / (CH * 18);
    int r = i % (CH * 18);
    int c = r / 18, co = r % 18;
    g_wo[i] = woff[(co * CH + c) * 9 + k];
}

// ---------- kernel 3: offset conv (proven 123us version) ----------
#define SMEM_B_FLOATS (130*129 + 3*CH*18)
__global__ void __launch_bounds__(256, 2) k_offconv(const float* __restrict__ b_off) {
    extern __shared__ float sm[];
    float* rowbuf  = sm;
    float* wsk     = sm + 130 * 129;
    float* partial = wsk;
    int h = blockIdx.x, b = blockIdx.y;
    int tid  = threadIdx.x;
    int lane = tid & 31, wrp = tid >> 5;
    int px    = tid & 127;
    int chalf = tid >> 7;
    int c0    = chalf * 64;

    unsigned long long acc[9];
    #pragma unroll
    for (int j = 0; j < 9; j++) acc[j] = 0ULL;

    for (int ky = 0; ky < 3; ky++) {
        int y = h + ky - 1;
        if ((unsigned)y >= HH) continue;
        __syncthreads();
        const float* src = g_xT + ((size_t)(b * HH + y) * WW) * CH;
        for (int pos = wrp; pos < 130; pos += 8) {
            int x = pos - 1;
            float4 v = make_float4(0.f, 0.f, 0.f, 0.f);
            if ((unsigned)x < WW) v = *(const float4*)(src + x * CH + 4 * lane);
            float* dst = rowbuf + pos * 129 + 4 * lane;
            dst[0] = v.x; dst[1] = v.y; dst[2] = v.z; dst[3] = v.w;
        }
        for (int i = tid; i < 3 * CH * 18; i += 256)
            wsk[i] = g_wo[ky * 3 * CH * 18 + i];
        __syncthreads();
        #pragma unroll
        for (int kx = 0; kx < 3; kx++) {
            const float* wk = wsk + kx * CH * 18;
            const float* rb = rowbuf + (px + kx) * 129;
            #pragma unroll 4
            for (int cc = 0; cc < 64; cc++) {
                int c = c0 + cc;
                float xv = rb[c];
                unsigned long long xv2 = pack2(xv, xv);
                const unsigned long long* w2 = (const unsigned long long*)(wk + c * 18);
                #pragma unroll
                for (int j = 0; j < 9; j++) fma2(acc[j], xv2, w2[j]);
            }
        }
    }
    __syncthreads();
    if (chalf == 1) {
        float* p = partial + px * 19;
        #pragma unroll
        for (int j = 0; j < 9; j++) {
            float2 v = unpack2(acc[j]);
            p[2 * j] = v.x; p[2 * j + 1] = v.y;
        }
    }
    __syncthreads();
    if (chalf == 0) {
        const float* p = partial + px * 19;
        int base = ((b * HH + h) * WW + px) * 18;
        #pragma unroll
        for (int j = 0; j < 9; j++) {
            float2 v = unpack2(acc[j]);
            g_off[base + 2 * j]     = v.x + p[2 * j]     + b_off[2 * j];
            g_off[base + 2 * j + 1] = v.y + p[2 * j + 1] + b_off[2 * j + 1];
        }
    }
}

// ---------- kernel 4: fp16 2-product mma.sync deformable conv + gate ----------
// C = Ah*B + Al*B, A split fp16 hi/lo (near-exact), B rounded to fp16 once.
// 64-px blocks, 128 threads (4 warps, m16n128 each), 73.5KB smem -> 3 CTAs/SM.
#define MTILE    64
#define LDA      136
#define LDAB     (LDA*2)          // 272 bytes per row
#define A_BYTES  (MTILE*LDAB)     // 17408
#define B_BYTES  (128*LDAB)       // 34816
#define OFF_OFFS  0               // 64*18*4 = 4608
#define OFF_BDEF  4608
#define OFF_WATTN 5120
#define OFF_A_HI  5632
#define OFF_A_LO  (OFF_A_HI + A_BYTES)
#define OFF_B     (OFF_A_LO + A_BYTES)
#define SMEM_MAIN_BYTES (OFF_B + B_BYTES)   // 75264

__global__ void __launch_bounds__(128, 3) k_main(const float* __restrict__ bdef,
                                                 const float* __restrict__ wattn,
                                                 const float* __restrict__ battn,
                                                 float* __restrict__ out) {
    extern __shared__ char smc[];
    uint32_t sb = smem_u32(smc);
    int h   = blockIdx.x >> 1;
    int px0 = (blockIdx.x & 1) << 6;
    int b   = blockIdx.y;
    int tid = threadIdx.x, lane = tid & 31, wid = tid >> 5;

    float* offs   = (float*)(smc + OFF_OFFS);
    float* sbdef  = (float*)(smc + OFF_BDEF);
    float* swattn = (float*)(smc + OFF_WATTN);

    for (int i = tid; i < 128; i += 128) { sbdef[i] = bdef[i]; swattn[i] = wattn[i]; }
    {
        const float* src = g_off + ((size_t)((b * HH + h) * WW) + px0) * 18;
        for (int i = tid; i < MTILE * 18; i += 128) offs[i] = src[i];
    }

    float acc[16][4];
    #pragma unroll
    for (int i = 0; i < 16; i++)
        #pragma unroll
        for (int j = 0; j < 4; j++) acc[i][j] = 0.f;

    const float* xb = g_xT + (size_t)b * HWSZ * CH + 4 * lane;

    // ldmatrix base addresses (rows local to this 64-px tile)
    int m0 = wid * 16;
    uint32_t aHi = sb + OFF_A_HI + (uint32_t)((m0 + (lane & 15)) * LDAB + (lane >> 4) * 16);
    uint32_t aLo = aHi + A_BYTES;
    // B (non-trans): matrices = [n0-7,k0] [n0-7,k8] [n8-15,k0] [n8-15,k8]
    uint32_t bRow = (uint32_t)((lane & 7) + ((lane >> 4) << 3));
    uint32_t bB = sb + OFF_B + bRow * LDAB + (((lane >> 3) & 1) << 4);

    for (int k = 0; k < 9; k++) {
        __syncthreads();   // previous-tap GEMM reads done; covers offs/bdef loads on k=0
        {   // stage B (fp16): [co][c] -> padded rows
            const uint4* sh = (const uint4*)(g_wtb + (size_t)k * COUT * CH);
            for (int i = tid; i < 2048; i += 128) {
                int row = i >> 4, c8 = i & 15;
                *(uint4*)(smc + OFF_B + row * LDAB + c8 * 16) = sh[i];
            }
        }
        // sample A (warp: 16 px, lane: channel quad), split fp32 -> fp16 hi+lo
        int ky = k / 3, kx = k % 3;
        #pragma unroll 2
        for (int it = 0; it < 16; it++) {
            int pl = wid * 16 + it;          // local row in A tile
            int px = px0 + pl;               // global pixel x
            float dy = offs[pl * 18 + 2 * k];
            float dx = offs[pl * 18 + 2 * k + 1];
            float ysf = (float)(h - 1 + ky) + dy;
            float xsf = (float)(px - 1 + kx) + dx;
            float y0f = floorf(ysf), x0f = floorf(xsf);
            float wy = ysf - y0f, wx = xsf - x0f;
            int y0 = (int)y0f, x0 = (int)x0f;
            float w00 = (1.f - wy) * (1.f - wx);
            float w01 = (1.f - wy) * wx;
            float w10 = wy * (1.f - wx);
            float w11 = wy * wx;
            float4 v = make_float4(0.f, 0.f, 0.f, 0.f);
            #define TAPG(Y, X, WGT) \
                if ((unsigned)(Y) < HH && (unsigned)(X) < WW) { \
                    float4 t = *(const float4*)(xb + ((Y) * WW + (X)) * CH); \
                    v.x = fmaf(WGT, t.x, v.x); v.y = fmaf(WGT, t.y, v.y); \
                    v.z = fmaf(WGT, t.z, v.z); v.w = fmaf(WGT, t.w, v.w); }
            TAPG(y0,     x0,     w00)
            TAPG(y0,     x0 + 1, w01)
            TAPG(y0 + 1, x0,     w10)
            TAPG(y0 + 1, x0 + 1, w11)
            #undef TAPG
            // fp16 split: hi = f16(v), lo = f16(v - hi). hi packs via f16x2 cvt.
            unsigned hu0 = packh2(v.y, v.x);
            unsigned hu1 = packh2(v.w, v.z);
            float2 h01 = __half22float2(*(__half2*)&hu0);
            float2 h23 = __half22float2(*(__half2*)&hu1);
            unsigned lu0 = packh2(v.y - h01.y, v.x - h01.x);
            unsigned lu1 = packh2(v.w - h23.y, v.z - h23.x);
            *(unsigned long long*)(smc + OFF_A_HI + pl * LDAB + 8 * lane) =
                ((unsigned long long)hu1 << 32) | hu0;
            *(unsigned long long*)(smc + OFF_A_LO + pl * LDAB + 8 * lane) =
                ((unsigned long long)lu1 << 32) | lu0;
        }
        __syncthreads();
        // GEMM: 8 K-chunks x 8 n-tile-pairs x 4 mma (AhB, AlB)
        #pragma unroll
        for (int kc = 0; kc < 8; kc++) {
            unsigned ah[4], al[4];
            ldsm4(ah, aHi + kc * 32);
            ldsm4(al, aLo + kc * 32);
            #pragma unroll
            for (int nt2 = 0; nt2 < 8; nt2++) {
                unsigned bh[4];
                ldsm4(bh, bB + nt2 * (16 * LDAB) + kc * 32);
                float* A0 = acc[nt2 * 2];
                float* A1 = acc[nt2 * 2 + 1];
                mma16816h(A0, ah, bh);
                mma16816h(A1, ah, bh + 2);
                mma16816h(A0, al, bh);
                mma16816h(A1, al, bh + 2);
            }
        }
    }

    // epilogue (register-only): bias, attention dot + quad shfl reduce, sigmoid, gate, store
    float battn0 = battn[0];
    float p0 = 0.f, p1 = 0.f;
    #pragma unroll
    for (int nt = 0; nt < 16; nt++) {
        int c0 = nt * 8 + (lane & 3) * 2;
        float bb0 = sbdef[c0], bb1 = sbdef[c0 + 1];
        float w0 = swattn[c0], w1 = swattn[c0 + 1];
        acc[nt][0] += bb0; acc[nt][1] += bb1;
        acc[nt][2] += bb0; acc[nt][3] += bb1;
        p0 = fmaf(acc[nt][0], w0, fmaf(acc[nt][1], w1, p0));
        p1 = fmaf(acc[nt][2], w0, fmaf(acc[nt][3], w1, p1));
    }
    p0 += __shfl_xor_sync(0xFFFFFFFFu, p0, 1);
    p0 += __shfl_xor_sync(0xFFFFFFFFu, p0, 2);
    p1 += __shfl_xor_sync(0xFFFFFFFFu, p1, 1);
    p1 += __shfl_xor_sync(0xFFFFFFFFu, p1, 2);
    float sig0 = 1.f / (1.f + expf(-(p0 + battn0)));
    float sig1 = 1.f / (1.f + expf(-(p1 + battn0)));

    int r0 = px0 + m0 + (lane >> 2);
    size_t obase = (size_t)b * COUT * HWSZ + (size_t)h * WW;
    #pragma unroll
    for (int nt = 0; nt < 16; nt++) {
        int c0 = nt * 8 + (lane & 3) * 2;
        out[obase + (size_t)c0       * HWSZ + r0]     = fmaxf(acc[nt][0] * sig0, 0.f);
        out[obase + (size_t)(c0 + 1) * HWSZ + r0]     = fmaxf(acc[nt][1] * sig0, 0.f);
        out[obase + (size_t)c0       * HWSZ + r0 + 8] = fmaxf(acc[nt][2] * sig1, 0.f);
        out[obase + (size_t)(c0 + 1) * HWSZ + r0 + 8] = fmaxf(acc[nt][3] * sig1, 0.f);
    }
}

// ---------- launch ----------
extern "C" void kernel_launch(void* const* d_in, const int* in_sizes, int n_in,
                              void* d_out, int out_size) {
    const float* x      = (const float*)d_in[0];
    const float* w_off  = (const float*)d_in[1];
    const float* b_off  = (const float*)d_in[2];
    const float* w_def  = (const float*)d_in[3];
    const float* b_def  = (const float*)d_in[4];
    const float* w_attn = (const float*)d_in[5];
    const float* b_attn = (const float*)d_in[6];
    float* out = (float*)d_out;

    static bool attrs_set = false;
    if (!attrs_set) {
        cudaFuncSetAttribute(k_offconv, cudaFuncAttributeMaxDynamicSharedMemorySize,
                             SMEM_B_FLOATS * sizeof(float));
        cudaFuncSetAttribute(k_main, cudaFuncAttributeMaxDynamicSharedMemorySize,
                             SMEM_MAIN_BYTES);
        attrs_set = true;
    }

    k_transpose<<<dim3(HWSZ / 32, CH / 32, BATCH), dim3(32, 8)>>>(x);
    k_reorder_wdefh<<<(9 * COUT * CH + 255) / 256, 256>>>(w_def);
    k_reorder_woff<<<(9 * CH * 18 + 255) / 256, 256>>>(w_off);
    k_offconv<<<dim3(HH, BATCH), 256, SMEM_B_FLOATS * sizeof(float)>>>(b_off);
    k_main<<<dim3(HH * 2, BATCH), 128, SMEM_MAIN_BYTES>>>(b_def, w_attn, b_attn, out);
}